// round 3
// baseline (speedup 1.0000x reference)
#include <cuda_runtime.h>
#include <math.h>

// Problem constants
#define BATCH 32
#define NSEQ  1024
#define DDIM  512
#define NHEAD 8
#define SCALE 0.04419417382415922f   // 1/sqrt(512)

// Scratch (device globals; allocation-free per harness rules)
__device__ float g_kh[(size_t)BATCH * NHEAD * NSEQ * DDIM];   // 512 MB
__device__ float g_vh[(size_t)BATCH * NHEAD * NSEQ * DDIM];   // 512 MB
__device__ float g_qh[(size_t)BATCH * NHEAD * NSEQ * DDIM];   // 512 MB
__device__ float g_s [(size_t)BATCH * NHEAD * NSEQ * NSEQ];   // 1 GB (scores -> probs in place)
__device__ float g_att[(size_t)BATCH * NHEAD * NSEQ * DDIM];  // 512 MB
__device__ float g_wot[(size_t)NHEAD * DDIM * DDIM];          // 8 MB (permuted Wo)

// GEMM tiling
#define BM  128
#define BNT 128
#define BK  16
#define TM  8
#define TN  8
#define NTHREADS 256

// ---------------------------------------------------------------------------
// Kernel 0: permute Wo[dd, e*H + h] -> Wo_t[(h*D + e)*D + dd]
// so the output projection becomes a plain NN GEMM with K iterated h-major.
// ---------------------------------------------------------------------------
__global__ void permute_wo_kernel(const float* __restrict__ Wo)
{
    int idx = blockIdx.x * blockDim.x + threadIdx.x;   // 0 .. H*D*D-1
    int dd = idx & (DDIM - 1);
    int t  = idx >> 9;          // h*D + e
    int e  = t & (DDIM - 1);
    int h  = t >> 9;
    g_wot[idx] = Wo[(size_t)dd * (NHEAD * DDIM) + e * NHEAD + h];
}

// ---------------------------------------------------------------------------
// Kernel 1: per-head projection (NT GEMM).
//   Y[b,h,n,e] = sum_d X[b,n,d] * W[h,e,d] + bias[h,e]
// P selects destination scratch: 0->kh, 1->vh, 2->qh
// grid: (BN*NSEQ/BM, DDIM/BNT, NHEAD)
// ---------------------------------------------------------------------------
template <int P>
__global__ __launch_bounds__(NTHREADS, 2)
void proj_kernel(const float* __restrict__ X, const float* __restrict__ W,
                 const float* __restrict__ bias)
{
    __shared__ __align__(16) float As[BK][BM + 4];
    __shared__ __align__(16) float Bs[BK][BNT + 4];

    float* Y = (P == 0) ? g_kh : (P == 1) ? g_vh : g_qh;

    const int h  = blockIdx.z;
    const int m0 = blockIdx.x * BM;     // global row in [0, B*N)
    const int e0 = blockIdx.y * BNT;
    const float* Wh = W + (size_t)h * DDIM * DDIM;

    const int tid = threadIdx.x;
    const int tm = tid >> 4, tn = tid & 15;
    const int lk = tid & 15, lr = tid >> 4;

    float acc[TM][TN];
#pragma unroll
    for (int i = 0; i < TM; i++)
#pragma unroll
        for (int j = 0; j < TN; j++) acc[i][j] = 0.f;

    for (int k0 = 0; k0 < DDIM; k0 += BK) {
#pragma unroll
        for (int p = 0; p < BM / 16; ++p)
            As[lk][lr + p * 16] = X[(size_t)(m0 + lr + p * 16) * DDIM + k0 + lk];
#pragma unroll
        for (int p = 0; p < BNT / 16; ++p)
            Bs[lk][lr + p * 16] = Wh[(size_t)(e0 + lr + p * 16) * DDIM + k0 + lk];
        __syncthreads();
#pragma unroll
        for (int kk = 0; kk < BK; ++kk) {
            float4 a0 = *(const float4*)(&As[kk][tm * TM]);
            float4 a1 = *(const float4*)(&As[kk][tm * TM + 4]);
            float4 b0 = *(const float4*)(&Bs[kk][tn * TN]);
            float4 b1 = *(const float4*)(&Bs[kk][tn * TN + 4]);
            float a[TM] = {a0.x, a0.y, a0.z, a0.w, a1.x, a1.y, a1.z, a1.w};
            float b[TN] = {b0.x, b0.y, b0.z, b0.w, b1.x, b1.y, b1.z, b1.w};
#pragma unroll
            for (int i = 0; i < TM; i++)
#pragma unroll
                for (int j = 0; j < TN; j++)
                    acc[i][j] = fmaf(a[i], b[j], acc[i][j]);
        }
        __syncthreads();
    }

    const int bb = m0 / NSEQ;            // block lies fully inside one batch
    const int n0 = m0 % NSEQ;
    float* Yb = Y + (((size_t)bb * NHEAD + h) * NSEQ) * DDIM;
#pragma unroll
    for (int i = 0; i < TM; i++) {
        int n = n0 + tm * TM + i;
#pragma unroll
        for (int j = 0; j < TN; j++) {
            int e = e0 + tn * TN + j;
            Yb[(size_t)n * DDIM + e] = acc[i][j] + bias[h * DDIM + e];
        }
    }
}

// ---------------------------------------------------------------------------
// Kernel 2: scores (NT GEMM): S[z,i,j] = (qh[z,i,:] . kh[z,j,:]) * SCALE
// grid: (NSEQ/BM, NSEQ/BNT, B*H)
// ---------------------------------------------------------------------------
__global__ __launch_bounds__(NTHREADS, 2)
void scores_kernel()
{
    __shared__ __align__(16) float As[BK][BM + 4];
    __shared__ __align__(16) float Bs[BK][BNT + 4];

    const size_t zb = (size_t)blockIdx.z * NSEQ * DDIM;
    const float* Q  = g_qh + zb;
    const float* Kh = g_kh + zb;
    float* S = g_s + (size_t)blockIdx.z * NSEQ * NSEQ;

    const int m0 = blockIdx.x * BM;     // query rows i
    const int j0 = blockIdx.y * BNT;    // key cols j
    const int tid = threadIdx.x;
    const int tm = tid >> 4, tn = tid & 15;
    const int lk = tid & 15, lr = tid >> 4;

    float acc[TM][TN];
#pragma unroll
    for (int i = 0; i < TM; i++)
#pragma unroll
        for (int j = 0; j < TN; j++) acc[i][j] = 0.f;

    for (int k0 = 0; k0 < DDIM; k0 += BK) {
#pragma unroll
        for (int p = 0; p < BM / 16; ++p)
            As[lk][lr + p * 16] = Q[(size_t)(m0 + lr + p * 16) * DDIM + k0 + lk];
#pragma unroll
        for (int p = 0; p < BNT / 16; ++p)
            Bs[lk][lr + p * 16] = Kh[(size_t)(j0 + lr + p * 16) * DDIM + k0 + lk];
        __syncthreads();
#pragma unroll
        for (int kk = 0; kk < BK; ++kk) {
            float4 a0 = *(const float4*)(&As[kk][tm * TM]);
            float4 a1 = *(const float4*)(&As[kk][tm * TM + 4]);
            float4 b0 = *(const float4*)(&Bs[kk][tn * TN]);
            float4 b1 = *(const float4*)(&Bs[kk][tn * TN + 4]);
            float a[TM] = {a0.x, a0.y, a0.z, a0.w, a1.x, a1.y, a1.z, a1.w};
            float b[TN] = {b0.x, b0.y, b0.z, b0.w, b1.x, b1.y, b1.z, b1.w};
#pragma unroll
            for (int i = 0; i < TM; i++)
#pragma unroll
                for (int j = 0; j < TN; j++)
                    acc[i][j] = fmaf(a[i], b[j], acc[i][j]);
        }
        __syncthreads();
    }

#pragma unroll
    for (int i = 0; i < TM; i++) {
        int gi = m0 + tm * TM + i;
#pragma unroll
        for (int j = 0; j < TN; j++)
            S[(size_t)gi * NSEQ + j0 + tn * TN + j] = acc[i][j] * SCALE;
    }
}

// ---------------------------------------------------------------------------
// Kernel 3: in-place row softmax over j (row length NSEQ).
// One block (128 threads) per row; 8 elements/thread.
// ---------------------------------------------------------------------------
__global__ __launch_bounds__(128)
void softmax_kernel()
{
    float* row = g_s + (size_t)blockIdx.x * NSEQ;
    const int tid = threadIdx.x;
    __shared__ float sm1[4], sm2[4];

    float v[8];
    float mx = -1e30f;
#pragma unroll
    for (int r = 0; r < 8; r++) { v[r] = row[tid + r * 128]; mx = fmaxf(mx, v[r]); }
#pragma unroll
    for (int o = 16; o; o >>= 1) mx = fmaxf(mx, __shfl_xor_sync(0xffffffffu, mx, o));
    if ((tid & 31) == 0) sm1[tid >> 5] = mx;
    __syncthreads();
    mx = fmaxf(fmaxf(sm1[0], sm1[1]), fmaxf(sm1[2], sm1[3]));

    float s = 0.f;
#pragma unroll
    for (int r = 0; r < 8; r++) { v[r] = __expf(v[r] - mx); s += v[r]; }
#pragma unroll
    for (int o = 16; o; o >>= 1) s += __shfl_xor_sync(0xffffffffu, s, o);
    if ((tid & 31) == 0) sm2[tid >> 5] = s;
    __syncthreads();
    s = sm2[0] + sm2[1] + sm2[2] + sm2[3];

    float inv = 1.f / s;
#pragma unroll
    for (int r = 0; r < 8; r++) row[tid + r * 128] = v[r] * inv;
}

// ---------------------------------------------------------------------------
// Kernel 4: att[z,i,e] = sum_j probs[z,i,j] * vh[z,j,e]   (NN GEMM, K=NSEQ)
// grid: (NSEQ/BM, DDIM/BNT, B*H)
// ---------------------------------------------------------------------------
__global__ __launch_bounds__(NTHREADS, 2)
void attout_kernel()
{
    __shared__ __align__(16) float As[BK][BM + 4];
    __shared__ __align__(16) float Bs[BK][BNT + 4];

    const float* Pz = g_s  + (size_t)blockIdx.z * NSEQ * NSEQ;
    const float* Vz = g_vh + (size_t)blockIdx.z * NSEQ * DDIM;
    float* Az = g_att + (size_t)blockIdx.z * NSEQ * DDIM;

    const int m0 = blockIdx.x * BM;     // query rows i
    const int e0 = blockIdx.y * BNT;    // output cols e
    const int tid = threadIdx.x;
    const int tm = tid >> 4, tn = tid & 15;
    const int lk = tid & 15, lr = tid >> 4;       // A loader
    const int lc = tid & 127, lkr = tid >> 7;     // B loader (NN)

    float acc[TM][TN];
#pragma unroll
    for (int i = 0; i < TM; i++)
#pragma unroll
        for (int j = 0; j < TN; j++) acc[i][j] = 0.f;

    for (int k0 = 0; k0 < NSEQ; k0 += BK) {
#pragma unroll
        for (int p = 0; p < BM / 16; ++p)
            As[lk][lr + p * 16] = Pz[(size_t)(m0 + lr + p * 16) * NSEQ + k0 + lk];
#pragma unroll
        for (int p = 0; p < BK / 2; ++p)
            Bs[lkr + p * 2][lc] = Vz[(size_t)(k0 + lkr + p * 2) * DDIM + e0 + lc];
        __syncthreads();
#pragma unroll
        for (int kk = 0; kk < BK; ++kk) {
            float4 a0 = *(const float4*)(&As[kk][tm * TM]);
            float4 a1 = *(const float4*)(&As[kk][tm * TM + 4]);
            float4 b0 = *(const float4*)(&Bs[kk][tn * TN]);
            float4 b1 = *(const float4*)(&Bs[kk][tn * TN + 4]);
            float a[TM] = {a0.x, a0.y, a0.z, a0.w, a1.x, a1.y, a1.z, a1.w};
            float b[TN] = {b0.x, b0.y, b0.z, b0.w, b1.x, b1.y, b1.z, b1.w};
#pragma unroll
            for (int i = 0; i < TM; i++)
#pragma unroll
                for (int j = 0; j < TN; j++)
                    acc[i][j] = fmaf(a[i], b[j], acc[i][j]);
        }
        __syncthreads();
    }

#pragma unroll
    for (int i = 0; i < TM; i++) {
        int gi = m0 + tm * TM + i;
#pragma unroll
        for (int j = 0; j < TN; j++)
            Az[(size_t)gi * DDIM + e0 + tn * TN + j] = acc[i][j];
    }
}

// ---------------------------------------------------------------------------
// Kernel 5: output projection (NN GEMM, K = H*D = 4096, h-chunked A).
//   out[b,n,dd] = sum_{h,e} att[b,h,n,e] * Wo_t[h*D+e, dd] + bo[dd]
// grid: (B*NSEQ/BM, DDIM/BNT)
// ---------------------------------------------------------------------------
__global__ __launch_bounds__(NTHREADS, 2)
void outproj_kernel(const float* __restrict__ bo, float* __restrict__ out)
{
    __shared__ __align__(16) float As[BK][BM + 4];
    __shared__ __align__(16) float Bs[BK][BNT + 4];

    const int m0  = blockIdx.x * BM;    // global row in [0, B*N)
    const int dd0 = blockIdx.y * BNT;
    const int bb  = m0 / NSEQ;
    const int n0  = m0 % NSEQ;

    const int tid = threadIdx.x;
    const int tm = tid >> 4, tn = tid & 15;
    const int lk = tid & 15, lr = tid >> 4;
    const int lc = tid & 127, lkr = tid >> 7;

    float acc[TM][TN];
#pragma unroll
    for (int i = 0; i < TM; i++)
#pragma unroll
        for (int j = 0; j < TN; j++) acc[i][j] = 0.f;

    for (int k0 = 0; k0 < NHEAD * DDIM; k0 += BK) {
        const int h  = k0 >> 9;          // K-tile lies within a single head chunk
        const int eb = k0 & (DDIM - 1);
        const float* Ab = g_att + (((size_t)bb * NHEAD + h) * NSEQ + n0) * DDIM + eb;
#pragma unroll
        for (int p = 0; p < BM / 16; ++p)
            As[lk][lr + p * 16] = Ab[(size_t)(lr + p * 16) * DDIM + lk];
#pragma unroll
        for (int p = 0; p < BK / 2; ++p)
            Bs[lkr + p * 2][lc] = g_wot[(size_t)(k0 + lkr + p * 2) * DDIM + dd0 + lc];
        __syncthreads();
#pragma unroll
        for (int kk = 0; kk < BK; ++kk) {
            float4 a0 = *(const float4*)(&As[kk][tm * TM]);
            float4 a1 = *(const float4*)(&As[kk][tm * TM + 4]);
            float4 b0 = *(const float4*)(&Bs[kk][tn * TN]);
            float4 b1 = *(const float4*)(&Bs[kk][tn * TN + 4]);
            float a[TM] = {a0.x, a0.y, a0.z, a0.w, a1.x, a1.y, a1.z, a1.w};
            float b[TN] = {b0.x, b0.y, b0.z, b0.w, b1.x, b1.y, b1.z, b1.w};
#pragma unroll
            for (int i = 0; i < TM; i++)
#pragma unroll
                for (int j = 0; j < TN; j++)
                    acc[i][j] = fmaf(a[i], b[j], acc[i][j]);
        }
        __syncthreads();
    }

#pragma unroll
    for (int i = 0; i < TM; i++) {
        int n = n0 + tm * TM + i;
#pragma unroll
        for (int j = 0; j < TN; j++) {
            int dd = dd0 + tn * TN + j;
            out[((size_t)bb * NSEQ + n) * DDIM + dd] = acc[i][j] + bo[dd];
        }
    }
}

// ---------------------------------------------------------------------------
extern "C" void kernel_launch(void* const* d_in, const int* in_sizes, int n_in,
                              void* d_out, int out_size)
{
    (void)in_sizes; (void)n_in; (void)out_size;
    const float* k_in = (const float*)d_in[0];
    const float* v_in = (const float*)d_in[1];
    const float* q_in = (const float*)d_in[2];
    const float* Wk   = (const float*)d_in[3];
    const float* bk   = (const float*)d_in[4];
    const float* Wv   = (const float*)d_in[5];
    const float* bv   = (const float*)d_in[6];
    const float* Wq   = (const float*)d_in[7];
    const float* bq   = (const float*)d_in[8];
    const float* Wo   = (const float*)d_in[9];
    const float* bo   = (const float*)d_in[10];
    float* out = (float*)d_out;

    // 0) permute Wo (8 MB)
    permute_wo_kernel<<<(NHEAD * DDIM * DDIM) / 256, 256>>>(Wo);

    // 1) QKV projections
    dim3 gproj(BATCH * NSEQ / BM, DDIM / BNT, NHEAD);
    proj_kernel<0><<<gproj, NTHREADS>>>(k_in, Wk, bk);
    proj_kernel<1><<<gproj, NTHREADS>>>(v_in, Wv, bv);
    proj_kernel<2><<<gproj, NTHREADS>>>(q_in, Wq, bq);

    // 2) scores
    dim3 gsc(NSEQ / BM, NSEQ / BNT, BATCH * NHEAD);
    scores_kernel<<<gsc, NTHREADS>>>();

    // 3) softmax (in place)
    softmax_kernel<<<BATCH * NHEAD * NSEQ, 128>>>();

    // 4) probs @ V
    dim3 gatt(NSEQ / BM, DDIM / BNT, BATCH * NHEAD);
    attout_kernel<<<gatt, NTHREADS>>>();

    // 5) output projection + bias
    dim3 gout(BATCH * NSEQ / BM, DDIM / BNT, 1);
    outproj_kernel<<<gout, NTHREADS>>>(bo, out);
}

// round 4
// speedup vs baseline: 2.6400x; 2.6400x over previous
#include <cuda_runtime.h>
#include <math.h>

// Problem constants
#define BATCH 32
#define NSEQ  1024
#define DDIM  512
#define NHEAD 8
#define SCALE 0.04419417382415922f   // 1/sqrt(512)

// Scratch (device globals; allocation-free per harness rules)
__device__ float g_kh[(size_t)BATCH * NHEAD * NSEQ * DDIM];
__device__ float g_vh[(size_t)BATCH * NHEAD * NSEQ * DDIM];
__device__ float g_qh[(size_t)BATCH * NHEAD * NSEQ * DDIM];
__device__ float g_s [(size_t)BATCH * NHEAD * NSEQ * NSEQ];
__device__ float g_att[(size_t)BATCH * NHEAD * NSEQ * DDIM];
__device__ float g_wot[(size_t)NHEAD * DDIM * DDIM];

// MMA GEMM tiling: block 128x128, BK=32, 8 warps (2m x 4n), warp tile 64x32
#define BM 128
#define BN 128
#define NTHREADS 256

// ---------------------------------------------------------------------------
// TF32 helpers
// ---------------------------------------------------------------------------
__device__ __forceinline__ unsigned f2tf(float f) {
    unsigned u;
    asm("cvt.rna.tf32.f32 %0, %1;" : "=r"(u) : "f"(f));
    return u;
}

__device__ __forceinline__ void mma_tf32(float* d, const unsigned* a, const unsigned* b) {
    asm volatile(
        "mma.sync.aligned.m16n8k8.row.col.f32.tf32.tf32.f32 "
        "{%0,%1,%2,%3}, {%4,%5,%6,%7}, {%8,%9}, {%0,%1,%2,%3};\n"
        : "+f"(d[0]), "+f"(d[1]), "+f"(d[2]), "+f"(d[3])
        : "r"(a[0]), "r"(a[1]), "r"(a[2]), "r"(a[3]), "r"(b[0]), "r"(b[1]));
}

// Swizzled smem word index: row stride 32 words, col ^ ((row&7)*4).
// Conflict-free for fragment LDS (lanes: g=row&7, tg=col low bits) and for
// 16B STS (phases of 8 lanes cover 8 distinct 4-bank groups).
__device__ __forceinline__ int swz(int r, int c) {
    return r * 32 + (c ^ ((r & 7) << 2));
}

// ---------------------------------------------------------------------------
// Staging: direct (source row-major [rows][ld], K contiguous)
// Tile = 128 rows x 32 k. 256 threads, 4 float4 each.
// ---------------------------------------------------------------------------
__device__ __forceinline__ void ldg_direct(float4 v[4], const float* __restrict__ src,
                                           int ld, int tid) {
    const int r0 = tid >> 3, c = (tid & 7) * 4;
#pragma unroll
    for (int p = 0; p < 4; p++)
        v[p] = *(const float4*)(src + (size_t)(r0 + p * 32) * ld + c);
}
__device__ __forceinline__ void sts_direct(unsigned* S, const float4 v[4], int tid) {
    const int r0 = tid >> 3, c = (tid & 7) * 4;
#pragma unroll
    for (int p = 0; p < 4; p++) {
        const int r = r0 + p * 32;
        uint4 u = make_uint4(f2tf(v[p].x), f2tf(v[p].y), f2tf(v[p].z), f2tf(v[p].w));
        *(uint4*)(S + r * 32 + (c ^ ((r & 7) << 2))) = u;
    }
}

// ---------------------------------------------------------------------------
// Staging: transposed (source row-major [K][ld], we need Bs[n][k])
// Tile = 32 k x 128 n. Thread t: n = t&127, k base = (t>>7)*16 (16 scalars).
// LDG coalesced along n; STS.128 conflict-free under the swizzle.
// ---------------------------------------------------------------------------
__device__ __forceinline__ void ldg_trans(float v[16], const float* __restrict__ src,
                                          int ld, int tid) {
    const int n = tid & 127, kb = (tid >> 7) * 16;
#pragma unroll
    for (int j = 0; j < 16; j++)
        v[j] = src[(size_t)(kb + j) * ld + n];
}
__device__ __forceinline__ void sts_trans(unsigned* S, const float v[16], int tid) {
    const int r = tid & 127, kb = (tid >> 7) * 16;
#pragma unroll
    for (int q = 0; q < 4; q++) {
        const int c = kb + q * 4;
        uint4 u = make_uint4(f2tf(v[q * 4]), f2tf(v[q * 4 + 1]),
                             f2tf(v[q * 4 + 2]), f2tf(v[q * 4 + 3]));
        *(uint4*)(S + r * 32 + (c ^ ((r & 7) << 2))) = u;
    }
}

// ---------------------------------------------------------------------------
// Warp-tile compute on one 128x128x32 staged tile.
// Warp tile 64x32: 4 m-tiles (16) x 4 n-tiles (8), 4 k8-steps -> 64 MMAs.
// ---------------------------------------------------------------------------
__device__ __forceinline__ void tile_mma(float acc[4][4][4],
                                         const unsigned* As, const unsigned* Bs,
                                         int wm, int wn, int g, int tg) {
#pragma unroll
    for (int ks = 0; ks < 4; ks++) {
        const int k0 = ks * 8;
        unsigned a[4][4], b[4][2];
#pragma unroll
        for (int mi = 0; mi < 4; mi++) {
            const int r = wm + mi * 16 + g;
            a[mi][0] = As[swz(r,     k0 + tg)];
            a[mi][1] = As[swz(r + 8, k0 + tg)];
            a[mi][2] = As[swz(r,     k0 + tg + 4)];
            a[mi][3] = As[swz(r + 8, k0 + tg + 4)];
        }
#pragma unroll
        for (int ni = 0; ni < 4; ni++) {
            const int c = wn + ni * 8 + g;
            b[ni][0] = Bs[swz(c, k0 + tg)];
            b[ni][1] = Bs[swz(c, k0 + tg + 4)];
        }
#pragma unroll
        for (int mi = 0; mi < 4; mi++)
#pragma unroll
            for (int ni = 0; ni < 4; ni++)
                mma_tf32(acc[mi][ni], a[mi], b[ni]);
    }
}

#define ZERO_ACC(acc)                          \
    _Pragma("unroll")                          \
    for (int mi = 0; mi < 4; mi++)             \
    _Pragma("unroll")                          \
    for (int ni = 0; ni < 4; ni++)             \
    _Pragma("unroll")                          \
    for (int q = 0; q < 4; q++) acc[mi][ni][q] = 0.f;

// ---------------------------------------------------------------------------
// Kernel 0: permute Wo[dd, e*H + h] -> Wo_t[(h*D + e)*D + dd]
// ---------------------------------------------------------------------------
__global__ void permute_wo_kernel(const float* __restrict__ Wo)
{
    int idx = blockIdx.x * blockDim.x + threadIdx.x;
    int dd = idx & (DDIM - 1);
    int t  = idx >> 9;
    int e  = t & (DDIM - 1);
    int h  = t >> 9;
    g_wot[idx] = Wo[(size_t)dd * (NHEAD * DDIM) + e * NHEAD + h];
}

// ---------------------------------------------------------------------------
// Kernel 1: per-head projection (NT): Y[b,h,n,e] = X[b,n,:].W[h,e,:] + bias
// grid: (B*N/128, D/128, H)
// ---------------------------------------------------------------------------
template <int P>
__global__ __launch_bounds__(NTHREADS)
void proj_kernel(const float* __restrict__ X, const float* __restrict__ W,
                 const float* __restrict__ bias)
{
    __shared__ __align__(16) unsigned As[BM * 32];
    __shared__ __align__(16) unsigned Bs[BN * 32];

    float* Y = (P == 0) ? g_kh : (P == 1) ? g_vh : g_qh;
    const int h  = blockIdx.z;
    const int m0 = blockIdx.x * BM;
    const int e0 = blockIdx.y * BN;
    const float* Asrc = X + (size_t)m0 * DDIM;
    const float* Bsrc = W + (size_t)h * DDIM * DDIM + (size_t)e0 * DDIM;

    const int tid = threadIdx.x;
    const int warp = tid >> 5, lane = tid & 31;
    const int wm = (warp >> 2) * 64, wn = (warp & 3) * 32;
    const int g = lane >> 2, tg = lane & 3;

    float acc[4][4][4];
    ZERO_ACC(acc);

    float4 pa[4], pb[4];
    ldg_direct(pa, Asrc, DDIM, tid);
    ldg_direct(pb, Bsrc, DDIM, tid);
    sts_direct(As, pa, tid);
    sts_direct(Bs, pb, tid);
    __syncthreads();

    const int KT = DDIM / 32;
    for (int kt = 0; kt < KT; kt++) {
        if (kt + 1 < KT) {
            ldg_direct(pa, Asrc + (kt + 1) * 32, DDIM, tid);
            ldg_direct(pb, Bsrc + (kt + 1) * 32, DDIM, tid);
        }
        tile_mma(acc, As, Bs, wm, wn, g, tg);
        __syncthreads();
        if (kt + 1 < KT) {
            sts_direct(As, pa, tid);
            sts_direct(Bs, pb, tid);
            __syncthreads();
        }
    }

    const int bb = m0 / NSEQ, n0 = m0 % NSEQ;
    float* Yb = Y + (((size_t)bb * NHEAD + h) * NSEQ + n0) * DDIM;
    const float* bh = bias + h * DDIM + e0;
#pragma unroll
    for (int mi = 0; mi < 4; mi++) {
        const int r = wm + mi * 16 + g;
#pragma unroll
        for (int ni = 0; ni < 4; ni++) {
            const int c = wn + ni * 8 + tg * 2;
            const float b0 = bh[c], b1 = bh[c + 1];
            *(float2*)(Yb + (size_t)r * DDIM + e0 + c) =
                make_float2(acc[mi][ni][0] + b0, acc[mi][ni][1] + b1);
            *(float2*)(Yb + (size_t)(r + 8) * DDIM + e0 + c) =
                make_float2(acc[mi][ni][2] + b0, acc[mi][ni][3] + b1);
        }
    }
}

// ---------------------------------------------------------------------------
// Kernel 2: scores (NT): S[z,i,j] = (qh[z,i,:].kh[z,j,:]) * SCALE
// grid: (N/128, N/128, B*H)
// ---------------------------------------------------------------------------
__global__ __launch_bounds__(NTHREADS)
void scores_kernel()
{
    __shared__ __align__(16) unsigned As[BM * 32];
    __shared__ __align__(16) unsigned Bs[BN * 32];

    const size_t zb = (size_t)blockIdx.z * NSEQ * DDIM;
    const float* Asrc = g_qh + zb + (size_t)blockIdx.x * BM * DDIM;
    const float* Bsrc = g_kh + zb + (size_t)blockIdx.y * BN * DDIM;
    float* S = g_s + (size_t)blockIdx.z * NSEQ * NSEQ;
    const int m0 = blockIdx.x * BM, j0 = blockIdx.y * BN;

    const int tid = threadIdx.x;
    const int warp = tid >> 5, lane = tid & 31;
    const int wm = (warp >> 2) * 64, wn = (warp & 3) * 32;
    const int g = lane >> 2, tg = lane & 3;

    float acc[4][4][4];
    ZERO_ACC(acc);

    float4 pa[4], pb[4];
    ldg_direct(pa, Asrc, DDIM, tid);
    ldg_direct(pb, Bsrc, DDIM, tid);
    sts_direct(As, pa, tid);
    sts_direct(Bs, pb, tid);
    __syncthreads();

    const int KT = DDIM / 32;
    for (int kt = 0; kt < KT; kt++) {
        if (kt + 1 < KT) {
            ldg_direct(pa, Asrc + (kt + 1) * 32, DDIM, tid);
            ldg_direct(pb, Bsrc + (kt + 1) * 32, DDIM, tid);
        }
        tile_mma(acc, As, Bs, wm, wn, g, tg);
        __syncthreads();
        if (kt + 1 < KT) {
            sts_direct(As, pa, tid);
            sts_direct(Bs, pb, tid);
            __syncthreads();
        }
    }

#pragma unroll
    for (int mi = 0; mi < 4; mi++) {
        const int r = m0 + wm + mi * 16 + g;
#pragma unroll
        for (int ni = 0; ni < 4; ni++) {
            const int c = j0 + wn + ni * 8 + tg * 2;
            *(float2*)(S + (size_t)r * NSEQ + c) =
                make_float2(acc[mi][ni][0] * SCALE, acc[mi][ni][1] * SCALE);
            *(float2*)(S + (size_t)(r + 8) * NSEQ + c) =
                make_float2(acc[mi][ni][2] * SCALE, acc[mi][ni][3] * SCALE);
        }
    }
}

// ---------------------------------------------------------------------------
// Kernel 3: in-place row softmax (row length NSEQ), 128 threads per row
// ---------------------------------------------------------------------------
__global__ __launch_bounds__(128)
void softmax_kernel()
{
    float* row = g_s + (size_t)blockIdx.x * NSEQ;
    const int tid = threadIdx.x;
    __shared__ float sm1[4], sm2[4];

    float v[8];
    float mx = -1e30f;
#pragma unroll
    for (int r = 0; r < 8; r++) { v[r] = row[tid + r * 128]; mx = fmaxf(mx, v[r]); }
#pragma unroll
    for (int o = 16; o; o >>= 1) mx = fmaxf(mx, __shfl_xor_sync(0xffffffffu, mx, o));
    if ((tid & 31) == 0) sm1[tid >> 5] = mx;
    __syncthreads();
    mx = fmaxf(fmaxf(sm1[0], sm1[1]), fmaxf(sm1[2], sm1[3]));

    float s = 0.f;
#pragma unroll
    for (int r = 0; r < 8; r++) { v[r] = __expf(v[r] - mx); s += v[r]; }
#pragma unroll
    for (int o = 16; o; o >>= 1) s += __shfl_xor_sync(0xffffffffu, s, o);
    if ((tid & 31) == 0) sm2[tid >> 5] = s;
    __syncthreads();
    s = sm2[0] + sm2[1] + sm2[2] + sm2[3];

    float inv = 1.f / s;
#pragma unroll
    for (int r = 0; r < 8; r++) row[tid + r * 128] = v[r] * inv;
}

// ---------------------------------------------------------------------------
// Kernel 4: att[z,i,e] = sum_j probs[z,i,j] * vh[z,j,e]  (NN, B transposed)
// grid: (N/128, D/128, B*H)
// ---------------------------------------------------------------------------
__global__ __launch_bounds__(NTHREADS)
void attout_kernel()
{
    __shared__ __align__(16) unsigned As[BM * 32];
    __shared__ __align__(16) unsigned Bs[BN * 32];

    const float* Asrc = g_s + (size_t)blockIdx.z * NSEQ * NSEQ
                            + (size_t)blockIdx.x * BM * NSEQ;
    const float* Vz = g_vh + (size_t)blockIdx.z * NSEQ * DDIM;
    float* Az = g_att + (size_t)blockIdx.z * NSEQ * DDIM;
    const int m0 = blockIdx.x * BM, e0 = blockIdx.y * BN;

    const int tid = threadIdx.x;
    const int warp = tid >> 5, lane = tid & 31;
    const int wm = (warp >> 2) * 64, wn = (warp & 3) * 32;
    const int g = lane >> 2, tg = lane & 3;

    float acc[4][4][4];
    ZERO_ACC(acc);

    float4 pa[4];
    float pv[16];
    ldg_direct(pa, Asrc, NSEQ, tid);
    ldg_trans(pv, Vz + e0, DDIM, tid);
    sts_direct(As, pa, tid);
    sts_trans(Bs, pv, tid);
    __syncthreads();

    const int KT = NSEQ / 32;
    for (int kt = 0; kt < KT; kt++) {
        if (kt + 1 < KT) {
            ldg_direct(pa, Asrc + (kt + 1) * 32, NSEQ, tid);
            ldg_trans(pv, Vz + (size_t)(kt + 1) * 32 * DDIM + e0, DDIM, tid);
        }
        tile_mma(acc, As, Bs, wm, wn, g, tg);
        __syncthreads();
        if (kt + 1 < KT) {
            sts_direct(As, pa, tid);
            sts_trans(Bs, pv, tid);
            __syncthreads();
        }
    }

#pragma unroll
    for (int mi = 0; mi < 4; mi++) {
        const int r = m0 + wm + mi * 16 + g;
#pragma unroll
        for (int ni = 0; ni < 4; ni++) {
            const int c = e0 + wn + ni * 8 + tg * 2;
            *(float2*)(Az + (size_t)r * DDIM + c) =
                make_float2(acc[mi][ni][0], acc[mi][ni][1]);
            *(float2*)(Az + (size_t)(r + 8) * DDIM + c) =
                make_float2(acc[mi][ni][2], acc[mi][ni][3]);
        }
    }
}

// ---------------------------------------------------------------------------
// Kernel 5: output projection (NN, K=H*D=4096, h-chunked A, B transposed)
// grid: (B*N/128, D/128)
// ---------------------------------------------------------------------------
__global__ __launch_bounds__(NTHREADS)
void outproj_kernel(const float* __restrict__ bo, float* __restrict__ out)
{
    __shared__ __align__(16) unsigned As[BM * 32];
    __shared__ __align__(16) unsigned Bs[BN * 32];

    const int m0  = blockIdx.x * BM;
    const int dd0 = blockIdx.y * BN;
    const int bb  = m0 / NSEQ, n0 = m0 % NSEQ;

    const int tid = threadIdx.x;
    const int warp = tid >> 5, lane = tid & 31;
    const int wm = (warp >> 2) * 64, wn = (warp & 3) * 32;
    const int g = lane >> 2, tg = lane & 3;

    float acc[4][4][4];
    ZERO_ACC(acc);

    float4 pa[4];
    float pv[16];
    {
        const float* Ab = g_att + (((size_t)bb * NHEAD + 0) * NSEQ + n0) * DDIM + 0;
        ldg_direct(pa, Ab, DDIM, tid);
        ldg_trans(pv, g_wot + dd0, DDIM, tid);
        sts_direct(As, pa, tid);
        sts_trans(Bs, pv, tid);
    }
    __syncthreads();

    const int KT = (NHEAD * DDIM) / 32;   // 128
    for (int kt = 0; kt < KT; kt++) {
        if (kt + 1 < KT) {
            const int k0n = (kt + 1) * 32;
            const int hn = k0n >> 9, ebn = k0n & (DDIM - 1);
            const float* Ab = g_att + (((size_t)bb * NHEAD + hn) * NSEQ + n0) * DDIM + ebn;
            ldg_direct(pa, Ab, DDIM, tid);
            ldg_trans(pv, g_wot + (size_t)k0n * DDIM + dd0, DDIM, tid);
        }
        tile_mma(acc, As, Bs, wm, wn, g, tg);
        __syncthreads();
        if (kt + 1 < KT) {
            sts_direct(As, pa, tid);
            sts_trans(Bs, pv, tid);
            __syncthreads();
        }
    }

#pragma unroll
    for (int mi = 0; mi < 4; mi++) {
        const int n = n0 + wm + mi * 16 + g;
#pragma unroll
        for (int ni = 0; ni < 4; ni++) {
            const int dd = dd0 + wn + ni * 8 + tg * 2;
            const float b0 = bo[dd], b1 = bo[dd + 1];
            *(float2*)(out + ((size_t)bb * NSEQ + n) * DDIM + dd) =
                make_float2(acc[mi][ni][0] + b0, acc[mi][ni][1] + b1);
            *(float2*)(out + ((size_t)bb * NSEQ + n + 8) * DDIM + dd) =
                make_float2(acc[mi][ni][2] + b0, acc[mi][ni][3] + b1);
        }
    }
}

// ---------------------------------------------------------------------------
extern "C" void kernel_launch(void* const* d_in, const int* in_sizes, int n_in,
                              void* d_out, int out_size)
{
    (void)in_sizes; (void)n_in; (void)out_size;
    const float* k_in = (const float*)d_in[0];
    const float* v_in = (const float*)d_in[1];
    const float* q_in = (const float*)d_in[2];
    const float* Wk   = (const float*)d_in[3];
    const float* bk   = (const float*)d_in[4];
    const float* Wv   = (const float*)d_in[5];
    const float* bv   = (const float*)d_in[6];
    const float* Wq   = (const float*)d_in[7];
    const float* bq   = (const float*)d_in[8];
    const float* Wo   = (const float*)d_in[9];
    const float* bo   = (const float*)d_in[10];
    float* out = (float*)d_out;

    permute_wo_kernel<<<(NHEAD * DDIM * DDIM) / 256, 256>>>(Wo);

    dim3 gproj(BATCH * NSEQ / BM, DDIM / BN, NHEAD);
    proj_kernel<0><<<gproj, NTHREADS>>>(k_in, Wk, bk);
    proj_kernel<1><<<gproj, NTHREADS>>>(v_in, Wv, bv);
    proj_kernel<2><<<gproj, NTHREADS>>>(q_in, Wq, bq);

    dim3 gsc(NSEQ / BM, NSEQ / BN, BATCH * NHEAD);
    scores_kernel<<<gsc, NTHREADS>>>();

    softmax_kernel<<<BATCH * NHEAD * NSEQ, 128>>>();

    dim3 gatt(NSEQ / BM, DDIM / BN, BATCH * NHEAD);
    attout_kernel<<<gatt, NTHREADS>>>();

    dim3 gout(BATCH * NSEQ / BM, DDIM / BN, 1);
    outproj_kernel<<<gout, NTHREADS>>>(bo, out);
}

// round 5
// speedup vs baseline: 4.6600x; 1.7651x over previous
#include <cuda_runtime.h>
#include <math.h>

// Problem constants
#define BATCH 32
#define NSEQ  1024
#define DDIM  512
#define NHEAD 8
#define SCALE 0.04419417382415922f   // 1/sqrt(512)

// ---------------------------------------------------------------------------
// Scratch (device globals; allocation-free per harness rules)
// ---------------------------------------------------------------------------
__device__ float g_kr [(size_t)BATCH * NSEQ * DDIM];          // rounded inputs
__device__ float g_vr [(size_t)BATCH * NSEQ * DDIM];
__device__ float g_qr [(size_t)BATCH * NSEQ * DDIM];
__device__ float g_wkr[(size_t)NHEAD * DDIM * DDIM];          // rounded weights
__device__ float g_wvr[(size_t)NHEAD * DDIM * DDIM];
__device__ float g_wqr[(size_t)NHEAD * DDIM * DDIM];
__device__ float g_kh [(size_t)BATCH * NHEAD * NSEQ * DDIM];  // projected (rounded)
__device__ float g_vh [(size_t)BATCH * NHEAD * NSEQ * DDIM];
__device__ float g_qh [(size_t)BATCH * NHEAD * NSEQ * DDIM];
__device__ float g_vt [(size_t)BATCH * NHEAD * DDIM * NSEQ];  // V transposed [z][e][j]
__device__ float g_s  [(size_t)BATCH * NHEAD * NSEQ * NSEQ];  // scores -> probs
__device__ float g_att[(size_t)BATCH * NHEAD * NSEQ * DDIM];  // attention out (rounded)
__device__ float g_wot[(size_t)NHEAD * DDIM * DDIM];          // Wo permuted+transposed [dd][h*D+e]

#define NTHREADS 256
#define SMEM_BYTES 65536   // 2 buffers x (A 16KB + B 16KB)

// ---------------------------------------------------------------------------
// Primitives
// ---------------------------------------------------------------------------
__device__ __forceinline__ unsigned f2tf(float f) {
    unsigned u;
    asm("cvt.rna.tf32.f32 %0, %1;" : "=r"(u) : "f"(f));
    return u;
}
__device__ __forceinline__ float rf(float f) { return __uint_as_float(f2tf(f)); }

__device__ __forceinline__ void store2r(float* p, float x, float y) {
    *(float2*)p = make_float2(rf(x), rf(y));
}

__device__ __forceinline__ void mma_tf32(float* d, const unsigned* a, const unsigned* b) {
    asm volatile(
        "mma.sync.aligned.m16n8k8.row.col.f32.tf32.tf32.f32 "
        "{%0,%1,%2,%3}, {%4,%5,%6,%7}, {%8,%9}, {%0,%1,%2,%3};\n"
        : "+f"(d[0]), "+f"(d[1]), "+f"(d[2]), "+f"(d[3])
        : "r"(a[0]), "r"(a[1]), "r"(a[2]), "r"(a[3]), "r"(b[0]), "r"(b[1]));
}

__device__ __forceinline__ void ldsm4(unsigned d[4], unsigned addr) {
    asm volatile("ldmatrix.sync.aligned.m8n8.x4.shared.b16 {%0,%1,%2,%3}, [%4];"
                 : "=r"(d[0]), "=r"(d[1]), "=r"(d[2]), "=r"(d[3]) : "r"(addr));
}

__device__ __forceinline__ void cp16(unsigned dst, const float* src) {
    asm volatile("cp.async.cg.shared.global [%0], [%1], 16;" :: "r"(dst), "l"(src));
}
#define CP_COMMIT() asm volatile("cp.async.commit_group;")
#define CP_WAIT1()  asm volatile("cp.async.wait_group 1;")

#define ZERO_ACC(acc)                          \
    _Pragma("unroll")                          \
    for (int mi = 0; mi < 4; mi++)             \
    _Pragma("unroll")                          \
    for (int ni = 0; ni < 4; ni++)             \
    _Pragma("unroll")                          \
    for (int q = 0; q < 4; q++) acc[mi][ni][q] = 0.f;

// ---------------------------------------------------------------------------
// Staging: one 128-row x 32-word tile via cp.async, XOR-4 swizzled.
// smem word index: r*32 + (c4 ^ ((r&7)<<2)); 16B chunks stay contiguous.
// ---------------------------------------------------------------------------
__device__ __forceinline__ void stage_tile(unsigned sb, const float* src, size_t ld,
                                           int sr, int sc4, int xs) {
#pragma unroll
    for (int p = 0; p < 4; p++) {
        const int r = sr + p * 32;                     // (r&7) == (sr&7)
        const unsigned dst = sb + (((r << 5) + (sc4 ^ xs)) << 2);
        cp16(dst, src + (size_t)r * ld + sc4);
    }
}

// ---------------------------------------------------------------------------
// Compute one staged 128x128x32 tile. Warp tile 64x32 (8 warps, 2m x 4n).
// Fragments via ldmatrix.x4; mapping verified against m16n8k8 tf32 layout.
// ---------------------------------------------------------------------------
__device__ __forceinline__ void tile_compute(unsigned bufA, float acc[4][4][4],
                                             int wm, int wn, int rA, int aoff, int xrA,
                                             int rB, int boff, int xrB) {
    const unsigned bufB = bufA + 16384u;
#pragma unroll
    for (int ks = 0; ks < 4; ks++) {
        unsigned a[4][4], b[2][4];
        const int ca = ((ks << 3) + aoff) ^ xrA;
        const int cb = ((ks << 3) + boff) ^ xrB;
#pragma unroll
        for (int mi = 0; mi < 4; mi++)
            ldsm4(a[mi], bufA + ((((wm + mi * 16 + rA) << 5) + ca) << 2));
#pragma unroll
        for (int p = 0; p < 2; p++)
            ldsm4(b[p], bufB + ((((wn + p * 16 + rB) << 5) + cb) << 2));
#pragma unroll
        for (int mi = 0; mi < 4; mi++)
#pragma unroll
            for (int ni = 0; ni < 4; ni++)
                mma_tf32(acc[mi][ni], a[mi], &b[ni >> 1][(ni & 1) << 1]);
    }
}

// ---------------------------------------------------------------------------
// Shared GEMM mainloop: 2-stage cp.async pipeline.
// A advances +32 per k-tile, except when ((kt+1)&aMask)==0 it advances aBig
// (aMask=0, aBig=32 for plain kernels; outproj uses head-chunk jumps).
// ---------------------------------------------------------------------------
__device__ __forceinline__ void gemm_loop(unsigned sbase,
                                          const float* pA, size_t ldA,
                                          const float* pB, size_t ldB,
                                          int KT, unsigned aMask, size_t aBig,
                                          float acc[4][4][4]) {
    const int tid = threadIdx.x;
    const int lane = tid & 31, warp = tid >> 5;
    const int wm = (warp >> 2) * 64, wn = (warp & 3) * 32;
    const int sr = tid >> 3, sc4 = (tid & 7) << 2, xs = (sr & 7) << 2;
    const int rA = lane & 15;
    const int aoff = (lane >> 4) << 2;
    const int xrA = (rA & 7) << 2;
    const int rB = ((lane >> 4) << 3) + (lane & 7);
    const int boff = ((lane >> 3) & 1) << 2;
    const int xrB = (lane & 7) << 2;

    stage_tile(sbase, pA, ldA, sr, sc4, xs);
    stage_tile(sbase + 16384u, pB, ldB, sr, sc4, xs);
    CP_COMMIT();

    for (int kt = 0; kt < KT; kt++) {
        if (kt + 1 < KT) {
            pA += (((unsigned)(kt + 1) & aMask) == 0u) ? aBig : 32;
            pB += 32;
            const unsigned nb = sbase + (((kt + 1) & 1) ? 32768u : 0u);
            stage_tile(nb, pA, ldA, sr, sc4, xs);
            stage_tile(nb + 16384u, pB, ldB, sr, sc4, xs);
        }
        CP_COMMIT();
        CP_WAIT1();
        __syncthreads();
        tile_compute(sbase + ((kt & 1) ? 32768u : 0u), acc,
                     wm, wn, rA, aoff, xrA, rB, boff, xrB);
        __syncthreads();
    }
}

// ---------------------------------------------------------------------------
// Kernel: round-copy a tensor to tf32-in-fp32 (pre-pass for GEMM operands)
// ---------------------------------------------------------------------------
template <int T>
__global__ void round_copy_kernel(const float* __restrict__ src, int n4)
{
    float* dst = (T == 0) ? g_kr : (T == 1) ? g_vr : (T == 2) ? g_qr
               : (T == 3) ? g_wkr : (T == 4) ? g_wvr : g_wqr;
    int i = blockIdx.x * blockDim.x + threadIdx.x;
    if (i < n4) {
        float4 v = ((const float4*)src)[i];
        ((float4*)dst)[i] = make_float4(rf(v.x), rf(v.y), rf(v.z), rf(v.w));
    }
}

// ---------------------------------------------------------------------------
// Kernel: permute+round Wo[dd, e*H+h] -> g_wot[dd][h*D+e]  (B for outproj)
// ---------------------------------------------------------------------------
__global__ void permute_wo_kernel(const float* __restrict__ Wo)
{
    int idx = blockIdx.x * blockDim.x + threadIdx.x;   // dd*4096 + h*512 + e
    int t  = idx & (NHEAD * DDIM - 1);
    int dd = idx >> 12;
    int e  = t & (DDIM - 1);
    int h  = t >> 9;
    g_wot[idx] = rf(Wo[(size_t)dd * (NHEAD * DDIM) + e * NHEAD + h]);
}

// ---------------------------------------------------------------------------
// Kernel: projection (NT): Y[b,h,n,e] = X[b,n,:].W[h,e,:] + bias, rounded
// grid: (B*N/128, D/128, H)
// ---------------------------------------------------------------------------
template <int P>
__global__ __launch_bounds__(NTHREADS, 2)
void proj_kernel(const float* __restrict__ bias)
{
    extern __shared__ __align__(16) unsigned char smem[];
    const unsigned sbase = (unsigned)__cvta_generic_to_shared(smem);

    const float* X = (P == 0) ? g_kr : (P == 1) ? g_vr : g_qr;
    const float* W = (P == 0) ? g_wkr : (P == 1) ? g_wvr : g_wqr;
    float* Y = (P == 0) ? g_kh : (P == 1) ? g_vh : g_qh;

    const int h = blockIdx.z, m0 = blockIdx.x * 128, e0 = blockIdx.y * 128;

    float acc[4][4][4];
    ZERO_ACC(acc);
    gemm_loop(sbase, X + (size_t)m0 * DDIM, DDIM,
              W + (size_t)h * DDIM * DDIM + (size_t)e0 * DDIM, DDIM,
              DDIM / 32, 0u, 32, acc);

    const int lane = threadIdx.x & 31, warp = threadIdx.x >> 5;
    const int wm = (warp >> 2) * 64, wn = (warp & 3) * 32;
    const int g = lane >> 2, tg = lane & 3;
    const int bb = m0 / NSEQ, n0 = m0 % NSEQ;
    float* Yb = Y + (((size_t)bb * NHEAD + h) * NSEQ + n0) * DDIM + e0;
    const float* bh = bias + h * DDIM + e0;
#pragma unroll
    for (int mi = 0; mi < 4; mi++) {
        const int r = wm + mi * 16 + g;
#pragma unroll
        for (int ni = 0; ni < 4; ni++) {
            const int c = wn + ni * 8 + tg * 2;
            const float b0 = bh[c], b1 = bh[c + 1];
            store2r(Yb + (size_t)r * DDIM + c, acc[mi][ni][0] + b0, acc[mi][ni][1] + b1);
            store2r(Yb + (size_t)(r + 8) * DDIM + c, acc[mi][ni][2] + b0, acc[mi][ni][3] + b1);
        }
    }
}

// ---------------------------------------------------------------------------
// Kernel: transpose V per (b,h): g_vt[z][e][j] = g_vh[z][j][e]
// grid: (N/32, D/32, B*H), block (32,8)
// ---------------------------------------------------------------------------
__global__ void transpose_v_kernel()
{
    __shared__ float t[32][33];
    const size_t zb = (size_t)blockIdx.z * NSEQ * DDIM;
    const int j0 = blockIdx.x * 32, e0 = blockIdx.y * 32;
    const float* src = g_vh + zb;
    float* dst = g_vt + zb;
#pragma unroll
    for (int k = 0; k < 32; k += 8)
        t[threadIdx.y + k][threadIdx.x] =
            src[(size_t)(j0 + threadIdx.y + k) * DDIM + e0 + threadIdx.x];
    __syncthreads();
#pragma unroll
    for (int k = 0; k < 32; k += 8)
        dst[(size_t)(e0 + threadIdx.y + k) * NSEQ + j0 + threadIdx.x] =
            t[threadIdx.x][threadIdx.y + k];
}

// ---------------------------------------------------------------------------
// Kernel: scores (NT): S[z,i,j] = (qh[z,i,:].kh[z,j,:]) * SCALE  (fp32 out)
// grid: (N/128, N/128, B*H)
// ---------------------------------------------------------------------------
__global__ __launch_bounds__(NTHREADS, 2)
void scores_kernel()
{
    extern __shared__ __align__(16) unsigned char smem[];
    const unsigned sbase = (unsigned)__cvta_generic_to_shared(smem);

    const size_t zb = (size_t)blockIdx.z * NSEQ * DDIM;
    const int m0 = blockIdx.x * 128, j0 = blockIdx.y * 128;
    float* S = g_s + (size_t)blockIdx.z * NSEQ * NSEQ;

    float acc[4][4][4];
    ZERO_ACC(acc);
    gemm_loop(sbase, g_qh + zb + (size_t)m0 * DDIM, DDIM,
              g_kh + zb + (size_t)j0 * DDIM, DDIM,
              DDIM / 32, 0u, 32, acc);

    const int lane = threadIdx.x & 31, warp = threadIdx.x >> 5;
    const int wm = (warp >> 2) * 64, wn = (warp & 3) * 32;
    const int g = lane >> 2, tg = lane & 3;
#pragma unroll
    for (int mi = 0; mi < 4; mi++) {
        const int r = m0 + wm + mi * 16 + g;
#pragma unroll
        for (int ni = 0; ni < 4; ni++) {
            const int c = j0 + wn + ni * 8 + tg * 2;
            *(float2*)(S + (size_t)r * NSEQ + c) =
                make_float2(acc[mi][ni][0] * SCALE, acc[mi][ni][1] * SCALE);
            *(float2*)(S + (size_t)(r + 8) * NSEQ + c) =
                make_float2(acc[mi][ni][2] * SCALE, acc[mi][ni][3] * SCALE);
        }
    }
}

// ---------------------------------------------------------------------------
// Kernel: in-place row softmax, output rounded to tf32
// ---------------------------------------------------------------------------
__global__ __launch_bounds__(128)
void softmax_kernel()
{
    float* row = g_s + (size_t)blockIdx.x * NSEQ;
    const int tid = threadIdx.x;
    __shared__ float sm1[4], sm2[4];

    float v[8];
    float mx = -1e30f;
#pragma unroll
    for (int r = 0; r < 8; r++) { v[r] = row[tid + r * 128]; mx = fmaxf(mx, v[r]); }
#pragma unroll
    for (int o = 16; o; o >>= 1) mx = fmaxf(mx, __shfl_xor_sync(0xffffffffu, mx, o));
    if ((tid & 31) == 0) sm1[tid >> 5] = mx;
    __syncthreads();
    mx = fmaxf(fmaxf(sm1[0], sm1[1]), fmaxf(sm1[2], sm1[3]));

    float s = 0.f;
#pragma unroll
    for (int r = 0; r < 8; r++) { v[r] = __expf(v[r] - mx); s += v[r]; }
#pragma unroll
    for (int o = 16; o; o >>= 1) s += __shfl_xor_sync(0xffffffffu, s, o);
    if ((tid & 31) == 0) sm2[tid >> 5] = s;
    __syncthreads();
    s = sm2[0] + sm2[1] + sm2[2] + sm2[3];

    const float inv = 1.f / s;
#pragma unroll
    for (int r = 0; r < 8; r++) row[tid + r * 128] = rf(v[r] * inv);
}

// ---------------------------------------------------------------------------
// Kernel: att[z,i,e] = sum_j probs[z,i,j] * vt[z,e,j]  (both K-contiguous)
// grid: (N/128, D/128, B*H). Output rounded.
// ---------------------------------------------------------------------------
__global__ __launch_bounds__(NTHREADS, 2)
void attout_kernel()
{
    extern __shared__ __align__(16) unsigned char smem[];
    const unsigned sbase = (unsigned)__cvta_generic_to_shared(smem);

    const int m0 = blockIdx.x * 128, e0 = blockIdx.y * 128;
    const float* Pz = g_s + (size_t)blockIdx.z * NSEQ * NSEQ + (size_t)m0 * NSEQ;
    const float* Vt = g_vt + (size_t)blockIdx.z * NSEQ * DDIM + (size_t)e0 * NSEQ;
    float* Az = g_att + (size_t)blockIdx.z * NSEQ * DDIM;

    float acc[4][4][4];
    ZERO_ACC(acc);
    gemm_loop(sbase, Pz, NSEQ, Vt, NSEQ, NSEQ / 32, 0u, 32, acc);

    const int lane = threadIdx.x & 31, warp = threadIdx.x >> 5;
    const int wm = (warp >> 2) * 64, wn = (warp & 3) * 32;
    const int g = lane >> 2, tg = lane & 3;
#pragma unroll
    for (int mi = 0; mi < 4; mi++) {
        const int r = m0 + wm + mi * 16 + g;
#pragma unroll
        for (int ni = 0; ni < 4; ni++) {
            const int c = e0 + wn + ni * 8 + tg * 2;
            store2r(Az + (size_t)r * DDIM + c, acc[mi][ni][0], acc[mi][ni][1]);
            store2r(Az + (size_t)(r + 8) * DDIM + c, acc[mi][ni][2], acc[mi][ni][3]);
        }
    }
}

// ---------------------------------------------------------------------------
// Kernel: output projection: out[b,n,dd] = sum_{h,e} att[b,h,n,e]*wot[dd,h*D+e] + bo
// grid: (B*N/128, D/128). A head-chunked (jump every 16 k-tiles).
// ---------------------------------------------------------------------------
__global__ __launch_bounds__(NTHREADS, 2)
void outproj_kernel(const float* __restrict__ bo, float* __restrict__ out)
{
    extern __shared__ __align__(16) unsigned char smem[];
    const unsigned sbase = (unsigned)__cvta_generic_to_shared(smem);

    const int m0 = blockIdx.x * 128, dd0 = blockIdx.y * 128;
    const int bb = m0 / NSEQ, n0 = m0 % NSEQ;

    float acc[4][4][4];
    ZERO_ACC(acc);
    // A: head h tile base = g_att[(bb*8+h)*N + n0][eb]; within-head step +32,
    // head boundary jump = N*512 - 480 floats.
    gemm_loop(sbase,
              g_att + (((size_t)bb * NHEAD + 0) * NSEQ + n0) * DDIM, DDIM,
              g_wot + (size_t)dd0 * (NHEAD * DDIM), NHEAD * DDIM,
              (NHEAD * DDIM) / 32, 15u, (size_t)NSEQ * DDIM - 480, acc);

    const int lane = threadIdx.x & 31, warp = threadIdx.x >> 5;
    const int wm = (warp >> 2) * 64, wn = (warp & 3) * 32;
    const int g = lane >> 2, tg = lane & 3;
#pragma unroll
    for (int mi = 0; mi < 4; mi++) {
        const int n = n0 + wm + mi * 16 + g;
#pragma unroll
        for (int ni = 0; ni < 4; ni++) {
            const int dd = dd0 + wn + ni * 8 + tg * 2;
            const float b0 = bo[dd], b1 = bo[dd + 1];
            *(float2*)(out + ((size_t)bb * NSEQ + n) * DDIM + dd) =
                make_float2(acc[mi][ni][0] + b0, acc[mi][ni][1] + b1);
            *(float2*)(out + ((size_t)bb * NSEQ + n + 8) * DDIM + dd) =
                make_float2(acc[mi][ni][2] + b0, acc[mi][ni][3] + b1);
        }
    }
}

// ---------------------------------------------------------------------------
extern "C" void kernel_launch(void* const* d_in, const int* in_sizes, int n_in,
                              void* d_out, int out_size)
{
    (void)in_sizes; (void)n_in; (void)out_size;
    const float* k_in = (const float*)d_in[0];
    const float* v_in = (const float*)d_in[1];
    const float* q_in = (const float*)d_in[2];
    const float* Wk   = (const float*)d_in[3];
    const float* bk   = (const float*)d_in[4];
    const float* Wv   = (const float*)d_in[5];
    const float* bv   = (const float*)d_in[6];
    const float* Wq   = (const float*)d_in[7];
    const float* bq   = (const float*)d_in[8];
    const float* Wo   = (const float*)d_in[9];
    const float* bo   = (const float*)d_in[10];
    float* out = (float*)d_out;

    // Opt-in 64KB dynamic smem for the GEMM kernels (idempotent host calls).
    cudaFuncSetAttribute((const void*)proj_kernel<0>, cudaFuncAttributeMaxDynamicSharedMemorySize, SMEM_BYTES);
    cudaFuncSetAttribute((const void*)proj_kernel<1>, cudaFuncAttributeMaxDynamicSharedMemorySize, SMEM_BYTES);
    cudaFuncSetAttribute((const void*)proj_kernel<2>, cudaFuncAttributeMaxDynamicSharedMemorySize, SMEM_BYTES);
    cudaFuncSetAttribute((const void*)scores_kernel,  cudaFuncAttributeMaxDynamicSharedMemorySize, SMEM_BYTES);
    cudaFuncSetAttribute((const void*)attout_kernel,  cudaFuncAttributeMaxDynamicSharedMemorySize, SMEM_BYTES);
    cudaFuncSetAttribute((const void*)outproj_kernel, cudaFuncAttributeMaxDynamicSharedMemorySize, SMEM_BYTES);

    // 0) round inputs + weights to tf32 values; permute Wo
    const int NXV4 = (BATCH * NSEQ * DDIM) / 4;
    const int NWV4 = (NHEAD * DDIM * DDIM) / 4;
    round_copy_kernel<0><<<(NXV4 + 255) / 256, 256>>>(k_in, NXV4);
    round_copy_kernel<1><<<(NXV4 + 255) / 256, 256>>>(v_in, NXV4);
    round_copy_kernel<2><<<(NXV4 + 255) / 256, 256>>>(q_in, NXV4);
    round_copy_kernel<3><<<(NWV4 + 255) / 256, 256>>>(Wk, NWV4);
    round_copy_kernel<4><<<(NWV4 + 255) / 256, 256>>>(Wv, NWV4);
    round_copy_kernel<5><<<(NWV4 + 255) / 256, 256>>>(Wq, NWV4);
    permute_wo_kernel<<<(NHEAD * DDIM * DDIM) / 256, 256>>>(Wo);

    // 1) QKV projections
    dim3 gproj(BATCH * NSEQ / 128, DDIM / 128, NHEAD);
    proj_kernel<0><<<gproj, NTHREADS, SMEM_BYTES>>>(bk);
    proj_kernel<1><<<gproj, NTHREADS, SMEM_BYTES>>>(bv);
    proj_kernel<2><<<gproj, NTHREADS, SMEM_BYTES>>>(bq);

    // 2) transpose V for K-contiguous B staging in attout
    dim3 gtv(NSEQ / 32, DDIM / 32, BATCH * NHEAD);
    transpose_v_kernel<<<gtv, dim3(32, 8)>>>();

    // 3) scores
    dim3 gsc(NSEQ / 128, NSEQ / 128, BATCH * NHEAD);
    scores_kernel<<<gsc, NTHREADS, SMEM_BYTES>>>();

    // 4) softmax (in place, rounds output)
    softmax_kernel<<<BATCH * NHEAD * NSEQ, 128>>>();

    // 5) probs @ V
    dim3 gatt(NSEQ / 128, DDIM / 128, BATCH * NHEAD);
    attout_kernel<<<gatt, NTHREADS, SMEM_BYTES>>>();

    // 6) output projection + bias
    dim3 gout(BATCH * NSEQ / 128, DDIM / 128, 1);
    outproj_kernel<<<gout, NTHREADS, SMEM_BYTES>>>(bo, out);
}

// round 6
// speedup vs baseline: 4.6701x; 1.0022x over previous
#include <cuda_runtime.h>
#include <math.h>

// Problem constants
#define BATCH 32
#define NSEQ  1024
#define DDIM  512
#define NHEAD 8
#define SCALE 0.04419417382415922f   // 1/sqrt(512)

// ---------------------------------------------------------------------------
// Scratch (device globals; allocation-free per harness rules)
// ---------------------------------------------------------------------------
__device__ float g_kr [(size_t)BATCH * NSEQ * DDIM];          // rounded inputs
__device__ float g_vr [(size_t)BATCH * NSEQ * DDIM];
__device__ float g_qr [(size_t)BATCH * NSEQ * DDIM];
__device__ float g_wkr[(size_t)NHEAD * DDIM * DDIM];          // rounded weights
__device__ float g_wvr[(size_t)NHEAD * DDIM * DDIM];
__device__ float g_wqr[(size_t)NHEAD * DDIM * DDIM];
__device__ float g_kh [(size_t)BATCH * NHEAD * NSEQ * DDIM];  // projected (rounded)
__device__ float g_vh [(size_t)BATCH * NHEAD * NSEQ * DDIM];
__device__ float g_qh [(size_t)BATCH * NHEAD * NSEQ * DDIM];  // pre-scaled by 1/sqrt(D)
__device__ float g_vt [(size_t)BATCH * NHEAD * DDIM * NSEQ];  // V transposed [z][e][j]
__device__ float g_s  [(size_t)BATCH * NHEAD * NSEQ * NSEQ];  // scores -> probs
__device__ float g_att[(size_t)BATCH * NHEAD * NSEQ * DDIM];  // attention out (rounded)
__device__ float g_wot[(size_t)NHEAD * DDIM * DDIM];          // Wo permuted+transposed [dd][h*D+e]

#define NTHREADS 256
#define STAGE_BYTES 32768u                 // A 16KB + B 16KB per stage
#define SMEM_BYTES (3 * STAGE_BYTES)       // 3-stage pipeline = 96KB

// ---------------------------------------------------------------------------
// Primitives
// ---------------------------------------------------------------------------
__device__ __forceinline__ unsigned f2tf(float f) {
    unsigned u;
    asm("cvt.rna.tf32.f32 %0, %1;" : "=r"(u) : "f"(f));
    return u;
}
__device__ __forceinline__ float rf(float f) { return __uint_as_float(f2tf(f)); }

__device__ __forceinline__ void store2r(float* p, float x, float y) {
    *(float2*)p = make_float2(rf(x), rf(y));
}

__device__ __forceinline__ void mma_tf32(float* d, const unsigned* a, const unsigned* b) {
    asm volatile(
        "mma.sync.aligned.m16n8k8.row.col.f32.tf32.tf32.f32 "
        "{%0,%1,%2,%3}, {%4,%5,%6,%7}, {%8,%9}, {%0,%1,%2,%3};\n"
        : "+f"(d[0]), "+f"(d[1]), "+f"(d[2]), "+f"(d[3])
        : "r"(a[0]), "r"(a[1]), "r"(a[2]), "r"(a[3]), "r"(b[0]), "r"(b[1]));
}

__device__ __forceinline__ void ldsm4(unsigned d[4], unsigned addr) {
    asm volatile("ldmatrix.sync.aligned.m8n8.x4.shared.b16 {%0,%1,%2,%3}, [%4];"
                 : "=r"(d[0]), "=r"(d[1]), "=r"(d[2]), "=r"(d[3]) : "r"(addr));
}

__device__ __forceinline__ void cp16(unsigned dst, const float* src) {
    asm volatile("cp.async.cg.shared.global [%0], [%1], 16;" :: "r"(dst), "l"(src));
}
#define CP_COMMIT() asm volatile("cp.async.commit_group;")
#define CP_WAIT1()  asm volatile("cp.async.wait_group 1;")

#define ZERO_ACC(acc)                          \
    _Pragma("unroll")                          \
    for (int mi = 0; mi < 4; mi++)             \
    _Pragma("unroll")                          \
    for (int ni = 0; ni < 4; ni++)             \
    _Pragma("unroll")                          \
    for (int q = 0; q < 4; q++) acc[mi][ni][q] = 0.f;

// ---------------------------------------------------------------------------
// Staging: one 128-row x 32-word tile via cp.async, XOR-4 swizzled.
// smem word index: r*32 + (c4 ^ ((r&7)<<2)); 16B chunks stay contiguous.
// ---------------------------------------------------------------------------
__device__ __forceinline__ void stage_tile(unsigned sb, const float* src, size_t ld,
                                           int sr, int sc4, int xs) {
#pragma unroll
    for (int p = 0; p < 4; p++) {
        const int r = sr + p * 32;                     // (r&7) == (sr&7)
        const unsigned dst = sb + (((r << 5) + (sc4 ^ xs)) << 2);
        cp16(dst, src + (size_t)r * ld + sc4);
    }
}

// ---------------------------------------------------------------------------
// Compute one staged 128x128x32 tile. Warp tile 64x32 (8 warps, 2m x 4n).
// ---------------------------------------------------------------------------
__device__ __forceinline__ void tile_compute(unsigned bufA, float acc[4][4][4],
                                             int wm, int wn, int rA, int aoff, int xrA,
                                             int rB, int boff, int xrB) {
    const unsigned bufB = bufA + 16384u;
#pragma unroll
    for (int ks = 0; ks < 4; ks++) {
        unsigned a[4][4], b[2][4];
        const int ca = ((ks << 3) + aoff) ^ xrA;
        const int cb = ((ks << 3) + boff) ^ xrB;
#pragma unroll
        for (int mi = 0; mi < 4; mi++)
            ldsm4(a[mi], bufA + ((((wm + mi * 16 + rA) << 5) + ca) << 2));
#pragma unroll
        for (int p = 0; p < 2; p++)
            ldsm4(b[p], bufB + ((((wn + p * 16 + rB) << 5) + cb) << 2));
#pragma unroll
        for (int mi = 0; mi < 4; mi++)
#pragma unroll
            for (int ni = 0; ni < 4; ni++)
                mma_tf32(acc[mi][ni], a[mi], &b[ni >> 1][(ni & 1) << 1]);
    }
}

// ---------------------------------------------------------------------------
// Shared GEMM mainloop: 3-stage cp.async pipeline, ONE sync per k-tile,
// staging for tile kt+2 issued BEFORE computing tile kt (overlap).
// A advance from tile t-1 to t: ((t & aMask)==0) ? aBig : 32 floats.
// ---------------------------------------------------------------------------
__device__ __forceinline__ void gemm_loop(unsigned sbase,
                                          const float* pA, size_t ldA,
                                          const float* pB, size_t ldB,
                                          int KT, unsigned aMask, size_t aBig,
                                          float acc[4][4][4]) {
    const int tid = threadIdx.x;
    const int lane = tid & 31, warp = tid >> 5;
    const int wm = (warp >> 2) * 64, wn = (warp & 3) * 32;
    const int sr = tid >> 3, sc4 = (tid & 7) << 2, xs = (sr & 7) << 2;
    const int rA = lane & 15;
    const int aoff = (lane >> 4) << 2;
    const int xrA = (rA & 7) << 2;
    const int rB = ((lane >> 4) << 3) + (lane & 7);
    const int boff = ((lane >> 3) & 1) << 2;
    const int xrB = (lane & 7) << 2;

    unsigned s0 = sbase, s1 = sbase + STAGE_BYTES, s2 = sbase + 2 * STAGE_BYTES;

    // Prologue: stage tiles 0 and 1 (pointers end at tile 1).
    stage_tile(s0, pA, ldA, sr, sc4, xs);
    stage_tile(s0 + 16384u, pB, ldB, sr, sc4, xs);
    CP_COMMIT();
    pA += ((1u & aMask) == 0u) ? aBig : 32;
    pB += 32;
    stage_tile(s1, pA, ldA, sr, sc4, xs);
    stage_tile(s1 + 16384u, pB, ldB, sr, sc4, xs);
    CP_COMMIT();

    for (int kt = 0; kt < KT; kt++) {
        CP_WAIT1();            // tile kt resident
        __syncthreads();       // also proves compute of tile kt-1 done by all warps
        if (kt + 2 < KT) {     // stage tile kt+2 into the slot freed by kt-1
            pA += (((unsigned)(kt + 2) & aMask) == 0u) ? aBig : 32;
            pB += 32;
            stage_tile(s2, pA, ldA, sr, sc4, xs);
            stage_tile(s2 + 16384u, pB, ldB, sr, sc4, xs);
        }
        CP_COMMIT();           // one group per iteration (possibly empty)
        tile_compute(s0, acc, wm, wn, rA, aoff, xrA, rB, boff, xrB);
        const unsigned t = s0; s0 = s1; s1 = s2; s2 = t;   // rotate slots
    }
}

// ---------------------------------------------------------------------------
// Kernel: round-copy a tensor to tf32-in-fp32 (pre-pass for GEMM operands)
// ---------------------------------------------------------------------------
template <int T>
__global__ void round_copy_kernel(const float* __restrict__ src, int n4)
{
    float* dst = (T == 0) ? g_kr : (T == 1) ? g_vr : (T == 2) ? g_qr
               : (T == 3) ? g_wkr : (T == 4) ? g_wvr : g_wqr;
    int i = blockIdx.x * blockDim.x + threadIdx.x;
    if (i < n4) {
        float4 v = ((const float4*)src)[i];
        ((float4*)dst)[i] = make_float4(rf(v.x), rf(v.y), rf(v.z), rf(v.w));
    }
}

// ---------------------------------------------------------------------------
// Kernel: permute+round Wo[dd, e*H+h] -> g_wot[dd][h*D+e]  (B for outproj)
// ---------------------------------------------------------------------------
__global__ void permute_wo_kernel(const float* __restrict__ Wo)
{
    int idx = blockIdx.x * blockDim.x + threadIdx.x;   // dd*4096 + h*512 + e
    int t  = idx & (NHEAD * DDIM - 1);
    int dd = idx >> 12;
    int e  = t & (DDIM - 1);
    int h  = t >> 9;
    g_wot[idx] = rf(Wo[(size_t)dd * (NHEAD * DDIM) + e * NHEAD + h]);
}

// ---------------------------------------------------------------------------
// Kernel: projection (NT): Y[b,h,n,e] = X[b,n,:].W[h,e,:] + bias, rounded.
// P==2 (Q) additionally pre-scales by 1/sqrt(D) so scores epilogue is a store.
// grid: (B*N/128, D/128, H)
// ---------------------------------------------------------------------------
template <int P>
__global__ __launch_bounds__(NTHREADS, 2)
void proj_kernel(const float* __restrict__ bias)
{
    extern __shared__ __align__(16) unsigned char smem[];
    const unsigned sbase = (unsigned)__cvta_generic_to_shared(smem);

    const float* X = (P == 0) ? g_kr : (P == 1) ? g_vr : g_qr;
    const float* W = (P == 0) ? g_wkr : (P == 1) ? g_wvr : g_wqr;
    float* Y = (P == 0) ? g_kh : (P == 1) ? g_vh : g_qh;
    const float postscale = (P == 2) ? SCALE : 1.0f;

    const int h = blockIdx.z, m0 = blockIdx.x * 128, e0 = blockIdx.y * 128;

    float acc[4][4][4];
    ZERO_ACC(acc);
    gemm_loop(sbase, X + (size_t)m0 * DDIM, DDIM,
              W + (size_t)h * DDIM * DDIM + (size_t)e0 * DDIM, DDIM,
              DDIM / 32, 0u, 32, acc);

    const int lane = threadIdx.x & 31, warp = threadIdx.x >> 5;
    const int wm = (warp >> 2) * 64, wn = (warp & 3) * 32;
    const int g = lane >> 2, tg = lane & 3;
    const int bb = m0 / NSEQ, n0 = m0 % NSEQ;
    float* Yb = Y + (((size_t)bb * NHEAD + h) * NSEQ + n0) * DDIM + e0;
    const float* bh = bias + h * DDIM + e0;
#pragma unroll
    for (int mi = 0; mi < 4; mi++) {
        const int r = wm + mi * 16 + g;
#pragma unroll
        for (int ni = 0; ni < 4; ni++) {
            const int c = wn + ni * 8 + tg * 2;
            const float b0 = bh[c], b1 = bh[c + 1];
            store2r(Yb + (size_t)r * DDIM + c,
                    (acc[mi][ni][0] + b0) * postscale, (acc[mi][ni][1] + b1) * postscale);
            store2r(Yb + (size_t)(r + 8) * DDIM + c,
                    (acc[mi][ni][2] + b0) * postscale, (acc[mi][ni][3] + b1) * postscale);
        }
    }
}

// ---------------------------------------------------------------------------
// Kernel: transpose V per (b,h): g_vt[z][e][j] = g_vh[z][j][e]
// grid: (N/32, D/32, B*H), block (32,8)
// ---------------------------------------------------------------------------
__global__ void transpose_v_kernel()
{
    __shared__ float t[32][33];
    const size_t zb = (size_t)blockIdx.z * NSEQ * DDIM;
    const int j0 = blockIdx.x * 32, e0 = blockIdx.y * 32;
    const float* src = g_vh + zb;
    float* dst = g_vt + zb;
#pragma unroll
    for (int k = 0; k < 32; k += 8)
        t[threadIdx.y + k][threadIdx.x] =
            src[(size_t)(j0 + threadIdx.y + k) * DDIM + e0 + threadIdx.x];
    __syncthreads();
#pragma unroll
    for (int k = 0; k < 32; k += 8)
        dst[(size_t)(e0 + threadIdx.y + k) * NSEQ + j0 + threadIdx.x] =
            t[threadIdx.x][threadIdx.y + k];
}

// ---------------------------------------------------------------------------
// Kernel: scores (NT): S[z,i,j] = qh[z,i,:].kh[z,j,:]  (qh pre-scaled)
// grid: (N/128, N/128, B*H)
// ---------------------------------------------------------------------------
__global__ __launch_bounds__(NTHREADS, 2)
void scores_kernel()
{
    extern __shared__ __align__(16) unsigned char smem[];
    const unsigned sbase = (unsigned)__cvta_generic_to_shared(smem);

    const size_t zb = (size_t)blockIdx.z * NSEQ * DDIM;
    const int m0 = blockIdx.x * 128, j0 = blockIdx.y * 128;
    float* S = g_s + (size_t)blockIdx.z * NSEQ * NSEQ;

    float acc[4][4][4];
    ZERO_ACC(acc);
    gemm_loop(sbase, g_qh + zb + (size_t)m0 * DDIM, DDIM,
              g_kh + zb + (size_t)j0 * DDIM, DDIM,
              DDIM / 32, 0u, 32, acc);

    const int lane = threadIdx.x & 31, warp = threadIdx.x >> 5;
    const int wm = (warp >> 2) * 64, wn = (warp & 3) * 32;
    const int g = lane >> 2, tg = lane & 3;
#pragma unroll
    for (int mi = 0; mi < 4; mi++) {
        const int r = m0 + wm + mi * 16 + g;
#pragma unroll
        for (int ni = 0; ni < 4; ni++) {
            const int c = j0 + wn + ni * 8 + tg * 2;
            *(float2*)(S + (size_t)r * NSEQ + c) =
                make_float2(acc[mi][ni][0], acc[mi][ni][1]);
            *(float2*)(S + (size_t)(r + 8) * NSEQ + c) =
                make_float2(acc[mi][ni][2], acc[mi][ni][3]);
        }
    }
}

// ---------------------------------------------------------------------------
// Kernel: in-place row softmax, output rounded to tf32
// ---------------------------------------------------------------------------
__global__ __launch_bounds__(128)
void softmax_kernel()
{
    float* row = g_s + (size_t)blockIdx.x * NSEQ;
    const int tid = threadIdx.x;
    __shared__ float sm1[4], sm2[4];

    float v[8];
    float mx = -1e30f;
#pragma unroll
    for (int r = 0; r < 8; r++) { v[r] = row[tid + r * 128]; mx = fmaxf(mx, v[r]); }
#pragma unroll
    for (int o = 16; o; o >>= 1) mx = fmaxf(mx, __shfl_xor_sync(0xffffffffu, mx, o));
    if ((tid & 31) == 0) sm1[tid >> 5] = mx;
    __syncthreads();
    mx = fmaxf(fmaxf(sm1[0], sm1[1]), fmaxf(sm1[2], sm1[3]));

    float s = 0.f;
#pragma unroll
    for (int r = 0; r < 8; r++) { v[r] = __expf(v[r] - mx); s += v[r]; }
#pragma unroll
    for (int o = 16; o; o >>= 1) s += __shfl_xor_sync(0xffffffffu, s, o);
    if ((tid & 31) == 0) sm2[tid >> 5] = s;
    __syncthreads();
    s = sm2[0] + sm2[1] + sm2[2] + sm2[3];

    const float inv = 1.f / s;
#pragma unroll
    for (int r = 0; r < 8; r++) row[tid + r * 128] = rf(v[r] * inv);
}

// ---------------------------------------------------------------------------
// Kernel: att[z,i,e] = sum_j probs[z,i,j] * vt[z,e,j]  (both K-contiguous)
// grid: (N/128, D/128, B*H). Output rounded.
// ---------------------------------------------------------------------------
__global__ __launch_bounds__(NTHREADS, 2)
void attout_kernel()
{
    extern __shared__ __align__(16) unsigned char smem[];
    const unsigned sbase = (unsigned)__cvta_generic_to_shared(smem);

    const int m0 = blockIdx.x * 128, e0 = blockIdx.y * 128;
    const float* Pz = g_s + (size_t)blockIdx.z * NSEQ * NSEQ + (size_t)m0 * NSEQ;
    const float* Vt = g_vt + (size_t)blockIdx.z * NSEQ * DDIM + (size_t)e0 * NSEQ;
    float* Az = g_att + (size_t)blockIdx.z * NSEQ * DDIM;

    float acc[4][4][4];
    ZERO_ACC(acc);
    gemm_loop(sbase, Pz, NSEQ, Vt, NSEQ, NSEQ / 32, 0u, 32, acc);

    const int lane = threadIdx.x & 31, warp = threadIdx.x >> 5;
    const int wm = (warp >> 2) * 64, wn = (warp & 3) * 32;
    const int g = lane >> 2, tg = lane & 3;
#pragma unroll
    for (int mi = 0; mi < 4; mi++) {
        const int r = m0 + wm + mi * 16 + g;
#pragma unroll
        for (int ni = 0; ni < 4; ni++) {
            const int c = e0 + wn + ni * 8 + tg * 2;
            store2r(Az + (size_t)r * DDIM + c, acc[mi][ni][0], acc[mi][ni][1]);
            store2r(Az + (size_t)(r + 8) * DDIM + c, acc[mi][ni][2], acc[mi][ni][3]);
        }
    }
}

// ---------------------------------------------------------------------------
// Kernel: output projection: out[b,n,dd] = sum_{h,e} att[b,h,n,e]*wot[dd,h*D+e] + bo
// grid: (B*N/128, D/128). A head-chunked (jump every 16 k-tiles).
// ---------------------------------------------------------------------------
__global__ __launch_bounds__(NTHREADS, 2)
void outproj_kernel(const float* __restrict__ bo, float* __restrict__ out)
{
    extern __shared__ __align__(16) unsigned char smem[];
    const unsigned sbase = (unsigned)__cvta_generic_to_shared(smem);

    const int m0 = blockIdx.x * 128, dd0 = blockIdx.y * 128;
    const int bb = m0 / NSEQ, n0 = m0 % NSEQ;

    float acc[4][4][4];
    ZERO_ACC(acc);
    gemm_loop(sbase,
              g_att + (((size_t)bb * NHEAD + 0) * NSEQ + n0) * DDIM, DDIM,
              g_wot + (size_t)dd0 * (NHEAD * DDIM), NHEAD * DDIM,
              (NHEAD * DDIM) / 32, 15u, (size_t)NSEQ * DDIM - 480, acc);

    const int lane = threadIdx.x & 31, warp = threadIdx.x >> 5;
    const int wm = (warp >> 2) * 64, wn = (warp & 3) * 32;
    const int g = lane >> 2, tg = lane & 3;
#pragma unroll
    for (int mi = 0; mi < 4; mi++) {
        const int n = n0 + wm + mi * 16 + g;
#pragma unroll
        for (int ni = 0; ni < 4; ni++) {
            const int dd = dd0 + wn + ni * 8 + tg * 2;
            const float b0 = bo[dd], b1 = bo[dd + 1];
            *(float2*)(out + ((size_t)bb * NSEQ + n) * DDIM + dd) =
                make_float2(acc[mi][ni][0] + b0, acc[mi][ni][1] + b1);
            *(float2*)(out + ((size_t)bb * NSEQ + n + 8) * DDIM + dd) =
                make_float2(acc[mi][ni][2] + b0, acc[mi][ni][3] + b1);
        }
    }
}

// ---------------------------------------------------------------------------
extern "C" void kernel_launch(void* const* d_in, const int* in_sizes, int n_in,
                              void* d_out, int out_size)
{
    (void)in_sizes; (void)n_in; (void)out_size;
    const float* k_in = (const float*)d_in[0];
    const float* v_in = (const float*)d_in[1];
    const float* q_in = (const float*)d_in[2];
    const float* Wk   = (const float*)d_in[3];
    const float* bk   = (const float*)d_in[4];
    const float* Wv   = (const float*)d_in[5];
    const float* bv   = (const float*)d_in[6];
    const float* Wq   = (const float*)d_in[7];
    const float* bq   = (const float*)d_in[8];
    const float* Wo   = (const float*)d_in[9];
    const float* bo   = (const float*)d_in[10];
    float* out = (float*)d_out;

    // Opt-in 96KB dynamic smem for the GEMM kernels (idempotent host calls).
    cudaFuncSetAttribute((const void*)proj_kernel<0>, cudaFuncAttributeMaxDynamicSharedMemorySize, SMEM_BYTES);
    cudaFuncSetAttribute((const void*)proj_kernel<1>, cudaFuncAttributeMaxDynamicSharedMemorySize, SMEM_BYTES);
    cudaFuncSetAttribute((const void*)proj_kernel<2>, cudaFuncAttributeMaxDynamicSharedMemorySize, SMEM_BYTES);
    cudaFuncSetAttribute((const void*)scores_kernel,  cudaFuncAttributeMaxDynamicSharedMemorySize, SMEM_BYTES);
    cudaFuncSetAttribute((const void*)attout_kernel,  cudaFuncAttributeMaxDynamicSharedMemorySize, SMEM_BYTES);
    cudaFuncSetAttribute((const void*)outproj_kernel, cudaFuncAttributeMaxDynamicSharedMemorySize, SMEM_BYTES);

    // 0) round inputs + weights to tf32 values; permute Wo
    const int NXV4 = (BATCH * NSEQ * DDIM) / 4;
    const int NWV4 = (NHEAD * DDIM * DDIM) / 4;
    round_copy_kernel<0><<<(NXV4 + 255) / 256, 256>>>(k_in, NXV4);
    round_copy_kernel<1><<<(NXV4 + 255) / 256, 256>>>(v_in, NXV4);
    round_copy_kernel<2><<<(NXV4 + 255) / 256, 256>>>(q_in, NXV4);
    round_copy_kernel<3><<<(NWV4 + 255) / 256, 256>>>(Wk, NWV4);
    round_copy_kernel<4><<<(NWV4 + 255) / 256, 256>>>(Wv, NWV4);
    round_copy_kernel<5><<<(NWV4 + 255) / 256, 256>>>(Wq, NWV4);
    permute_wo_kernel<<<(NHEAD * DDIM * DDIM) / 256, 256>>>(Wo);

    // 1) QKV projections (Q pre-scaled by 1/sqrt(D))
    dim3 gproj(BATCH * NSEQ / 128, DDIM / 128, NHEAD);
    proj_kernel<0><<<gproj, NTHREADS, SMEM_BYTES>>>(bk);
    proj_kernel<1><<<gproj, NTHREADS, SMEM_BYTES>>>(bv);
    proj_kernel<2><<<gproj, NTHREADS, SMEM_BYTES>>>(bq);

    // 2) transpose V for K-contiguous B staging in attout
    dim3 gtv(NSEQ / 32, DDIM / 32, BATCH * NHEAD);
    transpose_v_kernel<<<gtv, dim3(32, 8)>>>();

    // 3) scores
    dim3 gsc(NSEQ / 128, NSEQ / 128, BATCH * NHEAD);
    scores_kernel<<<gsc, NTHREADS, SMEM_BYTES>>>();

    // 4) softmax (in place, rounds output)
    softmax_kernel<<<BATCH * NHEAD * NSEQ, 128>>>();

    // 5) probs @ V
    dim3 gatt(NSEQ / 128, DDIM / 128, BATCH * NHEAD);
    attout_kernel<<<gatt, NTHREADS, SMEM_BYTES>>>();

    // 6) output projection + bias
    dim3 gout(BATCH * NSEQ / 128, DDIM / 128, 1);
    outproj_kernel<<<gout, NTHREADS, SMEM_BYTES>>>(bo, out);
}